// round 14
// baseline (speedup 1.0000x reference)
#include <cuda_runtime.h>
#include <math_constants.h>

#define THREADS 256
#define SEG 8192              // elements per block in all streaming passes
#define MAXB 4096
#define NELEM_MAX (1 << 24)   // 1*32*4096*128 = 2^24
#define NSLOT 64              // min/max atomic slots

// ---------------- device scratch (no allocations allowed) ----------------
__device__ unsigned int d_umin_arr[NSLOT] = {
    [0 ... NSLOT-1] = 0xFFFFFFFFu };            // re-armed by quanthist last block
__device__ unsigned int d_umax_arr[NSLOT];      // zero-init; re-armed likewise
__device__ int d_hist[256];                     // zeroed by next minmax
__device__ int d_bhT[256][MAXB];                // bin-major per-block histogram
__device__ unsigned char d_qbuf[NELEM_MAX];
__device__ float d_stats[3];                    // min, max, range
__device__ unsigned int d_done = 0;             // quanthist arrival counter

// order-preserving float <-> uint mapping for atomic min/max
__device__ __forceinline__ unsigned int enc_f(float f) {
    unsigned int u = __float_as_uint(f);
    return (u & 0x80000000u) ? ~u : (u | 0x80000000u);
}
__device__ __forceinline__ float dec_f(unsigned int e) {
    unsigned int u = (e & 0x80000000u) ? (e & 0x7FFFFFFFu) : ~e;
    return __uint_as_float(u);
}

// exact quantization matching jnp: ((x-min)/range)*255, round-half-even
__device__ __forceinline__ int quant(float v, float minv, float range) {
    float n = __fdiv_rn(v - minv, range);       // IEEE divide (no fast-math)
    float s = __fmul_rn(n, 255.0f);             // IEEE multiply
    int q = (int)rintf(s);                      // RNE, same as jnp.round
    return min(255, max(0, q));
}

__device__ __forceinline__ void mm4(float4 v, float& mn, float& mx) {
    mn = fminf(mn, fminf(fminf(v.x, v.y), fminf(v.z, v.w)));
    mx = fmaxf(mx, fmaxf(fmaxf(v.x, v.y), fmaxf(v.z, v.w)));
}

// warp-aggregated histogram add: lanes with equal q merge; leader does ONE
// conflict-free single-lane ATOMS with the popc. Requires full-warp convergence.
__device__ __forceinline__ void hist_agg(int* hist, int q, int lane) {
    unsigned int mk = __match_any_sync(0xFFFFFFFFu, q);
    if (lane == __ffs(mk) - 1) atomicAdd(&hist[q], __popc(mk));
}

// ---------------- pass 1: global min/max (MLP=8) + d_hist re-arm ----------
__global__ void __launch_bounds__(THREADS)
k_minmax(const float* __restrict__ x, int n) {
    int tid = threadIdx.x;
    if (blockIdx.x == 0) d_hist[tid] = 0;   // re-arm for this run's quanthist
    int base = blockIdx.x * SEG;
    float mn = CUDART_INF_F, mx = -CUDART_INF_F;

    if (base + SEG <= n) {
        float4 v[8];
#pragma unroll
        for (int j = 0; j < 8; j++)
            v[j] = *reinterpret_cast<const float4*>(x + base + j * 1024 + tid * 4);
        float mn0 = CUDART_INF_F, mx0 = -CUDART_INF_F;
        float mn1 = CUDART_INF_F, mx1 = -CUDART_INF_F;
#pragma unroll
        for (int j = 0; j < 8; j += 2) {
            mm4(v[j],     mn0, mx0);
            mm4(v[j + 1], mn1, mx1);
        }
        mn = fminf(mn0, mn1);
        mx = fmaxf(mx0, mx1);
    } else {
        for (int i = base + tid; i < n; i += THREADS) {
            float vv = x[i];
            mn = fminf(mn, vv);
            mx = fmaxf(mx, vv);
        }
    }
#pragma unroll
    for (int o = 16; o; o >>= 1) {
        mn = fminf(mn, __shfl_xor_sync(0xFFFFFFFFu, mn, o));
        mx = fmaxf(mx, __shfl_xor_sync(0xFFFFFFFFu, mx, o));
    }
    __shared__ float smin[8], smax[8];
    int lane = tid & 31, wid = tid >> 5;
    if (lane == 0) { smin[wid] = mn; smax[wid] = mx; }
    __syncthreads();
    if (tid == 0) {
#pragma unroll
        for (int w = 1; w < 8; w++) {
            mn = fminf(mn, smin[w]);
            mx = fmaxf(mx, smax[w]);
        }
        int slot = blockIdx.x & (NSLOT - 1);    // 64-way spread: no hot address
        atomicMin(&d_umin_arr[slot], enc_f(mn));
        atomicMax(&d_umax_arr[slot], enc_f(mx));
        __threadfence();
    }
    cudaTriggerProgrammaticLaunchCompletion();
}

// ---------------- pass 2: quantize + histogram (warp-aggregated atomics) --
__global__ void __launch_bounds__(THREADS)
k_quanthist(const float* __restrict__ x, int n) {
    __shared__ int sh[8][256];    // one hist per warp (8 KB)
    __shared__ unsigned int s_mm[2];
    int tid = threadIdx.x;
    int lane = tid & 31, wid = tid >> 5;
    int* hist = sh[wid];
#pragma unroll
    for (int i = tid; i < 8 * 256; i += THREADS) ((int*)sh)[i] = 0;

    int base = blockIdx.x * SEG;
    bool full = (base + SEG <= n);

    // prefetch iteration 0 (x is input-only: legal before the PDL sync)
    float4 p0, p1, p2, p3;
    if (full) {
        int i0 = base + tid * 4;
        p0 = __ldcs(reinterpret_cast<const float4*>(x + i0));
        p1 = __ldcs(reinterpret_cast<const float4*>(x + i0 + 1024));
        p2 = __ldcs(reinterpret_cast<const float4*>(x + i0 + 2048));
        p3 = __ldcs(reinterpret_cast<const float4*>(x + i0 + 3072));
    }

    // wait for k_minmax grid to complete (PDL)
    cudaGridDependencySynchronize();

    // combine the 64 min/max slots (warp 0), broadcast via smem
    if (wid == 0) {
        unsigned int um = min(d_umin_arr[lane], d_umin_arr[lane + 32]);
        unsigned int ux = max(d_umax_arr[lane], d_umax_arr[lane + 32]);
#pragma unroll
        for (int o = 16; o; o >>= 1) {
            um = min(um, __shfl_xor_sync(0xFFFFFFFFu, um, o));
            ux = max(ux, __shfl_xor_sync(0xFFFFFFFFu, ux, o));
        }
        if (lane == 0) { s_mm[0] = um; s_mm[1] = ux; }
    }
    __syncthreads();
    float minv = dec_f(s_mm[0]), maxv = dec_f(s_mm[1]);
    float range = maxv - minv;
    if (range == 0.0f) range = 1.0f;

    // last-arriving block re-arms slots + snapshots stats (no waiting).
    if (tid == 0) {
        unsigned int prev = atomicAdd(&d_done, 1u);
        if (prev == (unsigned int)(gridDim.x - 1)) {
            d_stats[0] = minv;
            d_stats[1] = maxv;
            d_stats[2] = range;
#pragma unroll
            for (int i = 0; i < NSLOT; i++) {
                d_umin_arr[i] = 0xFFFFFFFFu;
                d_umax_arr[i] = 0u;
            }
            d_done = 0;
        }
    }

    if (full) {
#pragma unroll
        for (int k = 0; k < SEG; k += 4096) {
            int i0 = base + k + tid * 4;
            float4 v0, v1, v2, v3;
            if (k == 0) { v0 = p0; v1 = p1; v2 = p2; v3 = p3; }
            else {
                v0 = __ldcs(reinterpret_cast<const float4*>(x + i0));
                v1 = __ldcs(reinterpret_cast<const float4*>(x + i0 + 1024));
                v2 = __ldcs(reinterpret_cast<const float4*>(x + i0 + 2048));
                v3 = __ldcs(reinterpret_cast<const float4*>(x + i0 + 3072));
            }

            int q00 = quant(v0.x, minv, range), q01 = quant(v0.y, minv, range);
            int q02 = quant(v0.z, minv, range), q03 = quant(v0.w, minv, range);
            int q10 = quant(v1.x, minv, range), q11 = quant(v1.y, minv, range);
            int q12 = quant(v1.z, minv, range), q13 = quant(v1.w, minv, range);
            int q20 = quant(v2.x, minv, range), q21 = quant(v2.y, minv, range);
            int q22 = quant(v2.z, minv, range), q23 = quant(v2.w, minv, range);
            int q30 = quant(v3.x, minv, range), q31 = quant(v3.y, minv, range);
            int q32 = quant(v3.z, minv, range), q33 = quant(v3.w, minv, range);

            hist_agg(hist, q00, lane); hist_agg(hist, q01, lane);
            hist_agg(hist, q02, lane); hist_agg(hist, q03, lane);
            hist_agg(hist, q10, lane); hist_agg(hist, q11, lane);
            hist_agg(hist, q12, lane); hist_agg(hist, q13, lane);
            hist_agg(hist, q20, lane); hist_agg(hist, q21, lane);
            hist_agg(hist, q22, lane); hist_agg(hist, q23, lane);
            hist_agg(hist, q30, lane); hist_agg(hist, q31, lane);
            hist_agg(hist, q32, lane); hist_agg(hist, q33, lane);

            *reinterpret_cast<uchar4*>(d_qbuf + i0) =
                make_uchar4((unsigned char)q00, (unsigned char)q01,
                            (unsigned char)q02, (unsigned char)q03);
            *reinterpret_cast<uchar4*>(d_qbuf + i0 + 1024) =
                make_uchar4((unsigned char)q10, (unsigned char)q11,
                            (unsigned char)q12, (unsigned char)q13);
            *reinterpret_cast<uchar4*>(d_qbuf + i0 + 2048) =
                make_uchar4((unsigned char)q20, (unsigned char)q21,
                            (unsigned char)q22, (unsigned char)q23);
            *reinterpret_cast<uchar4*>(d_qbuf + i0 + 3072) =
                make_uchar4((unsigned char)q30, (unsigned char)q31,
                            (unsigned char)q32, (unsigned char)q33);
        }
    } else {
        for (int j = base + tid; j < n; j += THREADS) {
            int q = quant(x[j], minv, range);
            atomicAdd(&hist[q], 1);           // tail: plain atomics (partial warp)
            d_qbuf[j] = (unsigned char)q;
        }
    }
    __syncthreads();
    int tot = 0;
#pragma unroll
    for (int w = 0; w < 8; w++) tot += sh[w][tid];
    atomicAdd(&d_hist[tid], tot);
    d_bhT[tid][blockIdx.x] = tot;     // bin-major: column t is contiguous
    __threadfence();
    cudaTriggerProgrammaticLaunchCompletion();
}

// ---------------- pass 3: per-block selection + sparsified output ---------
__global__ void __launch_bounds__(THREADS)
k_output(float* __restrict__ out, int n, int keep, long long out_n) {
    __shared__ int sc[256];
    __shared__ int s_tr[2];
    __shared__ int red[8];
    int tid = threadIdx.x;
    int lane = tid & 31, wid = tid >> 5;
    int b = blockIdx.x;
    int warpbase = b * SEG + wid * 1024;

    // wait for k_quanthist grid — PDL
    cudaGridDependencySynchronize();

    // --- redundant threshold selection (parallel across all blocks) ---
    int h = d_hist[tid];
    sc[tid] = h;
    __syncthreads();
#pragma unroll
    for (int off = 1; off < 256; off <<= 1) {
        int add = (tid + off < 256) ? sc[tid + off] : 0;
        __syncthreads();
        sc[tid] += add;
        __syncthreads();
    }
    {
        int ge = sc[tid];
        int gt = ge - h;
        if (gt < keep && ge >= keep) { s_tr[0] = tid; s_tr[1] = keep - gt; }
    }
    __syncthreads();
    int t = s_tr[0], r = s_tr[1];

    // --- own tie prefix: s = sum d_bhT[t][0..b), contiguous L2-hot ---
    const int* col = d_bhT[t];
    int part = 0;
    for (int j = tid; j < b; j += THREADS) part += col[j];
#pragma unroll
    for (int o = 16; o; o >>= 1) part += __shfl_xor_sync(0xFFFFFFFFu, part, o);
    if (lane == 0) red[wid] = part;
    __syncthreads();
    int s = red[0];
#pragma unroll
    for (int w = 1; w < 8; w++) s += red[w];
    int e = s + col[b];

    if (e <= r || s >= r) {
        // ---- fast path: keep q >= keepv, front-batched loads (MLP=8) ----
        int keepv = (e <= r) ? t : (t + 1);
        if (b * SEG + SEG <= n) {
            uchar4 qv[8];
#pragma unroll
            for (int rr = 0; rr < 8; rr++)
                qv[rr] = *reinterpret_cast<const uchar4*>(
                    d_qbuf + warpbase + rr * 128 + lane * 4);
#pragma unroll
            for (int rr = 0; rr < 8; rr++) {
                uchar4 q = qv[rr];
                float4 ov;
                ov.x = (q.x >= keepv) ? (float)q.x : 0.0f;
                ov.y = (q.y >= keepv) ? (float)q.y : 0.0f;
                ov.z = (q.z >= keepv) ? (float)q.z : 0.0f;
                ov.w = (q.w >= keepv) ? (float)q.w : 0.0f;
                __stcs(reinterpret_cast<float4*>(out + warpbase + rr * 128 + lane * 4), ov);
            }
        } else {
            for (int rr = 0; rr < 8; rr++) {
                int idx = warpbase + rr * 128 + lane * 4;
                for (int m = 0; m < 4; m++) {
                    int j = idx + m;
                    if (j < n) {
                        int q = d_qbuf[j];
                        out[j] = (q >= keepv) ? (float)q : 0.0f;
                    }
                }
            }
        }
    } else {
        // ---- partial path: exactly one block — two-phase ballot ranking ----
        __shared__ int s_wtot[8];
        unsigned int ltmask = (1u << lane) - 1u;

        int wcnt = 0;
#pragma unroll
        for (int rr = 0; rr < 8; rr++) {
            int idx = warpbase + rr * 128 + lane * 4;
            uchar4 q = make_uchar4(255, 255, 255, 255);
            unsigned int m = 0;
            if (idx + 3 < n) {
                q = *reinterpret_cast<const uchar4*>(d_qbuf + idx);
                m = 0xFu;
            } else {
                if (idx + 0 < n) { q.x = d_qbuf[idx + 0]; m |= 1u; }
                if (idx + 1 < n) { q.y = d_qbuf[idx + 1]; m |= 2u; }
                if (idx + 2 < n) { q.z = d_qbuf[idx + 2]; m |= 4u; }
            }
            unsigned int b0 = __ballot_sync(0xFFFFFFFFu, (m & 1u) && q.x == t);
            unsigned int b1 = __ballot_sync(0xFFFFFFFFu, (m & 2u) && q.y == t);
            unsigned int b2 = __ballot_sync(0xFFFFFFFFu, (m & 4u) && q.z == t);
            unsigned int b3 = __ballot_sync(0xFFFFFFFFu, (m & 8u) && q.w == t);
            wcnt += __popc(b0) + __popc(b1) + __popc(b2) + __popc(b3);
        }
        if (lane == 0) s_wtot[wid] = wcnt;
        __syncthreads();

        int wbase = s;
#pragma unroll
        for (int w = 0; w < 8; w++)
            if (w < wid) wbase += s_wtot[w];

        int run = 0;
#pragma unroll
        for (int rr = 0; rr < 8; rr++) {
            int idx = warpbase + rr * 128 + lane * 4;
            uchar4 q = make_uchar4(255, 255, 255, 255);
            unsigned int m = 0;
            if (idx + 3 < n) {
                q = *reinterpret_cast<const uchar4*>(d_qbuf + idx);
                m = 0xFu;
            } else {
                if (idx + 0 < n) { q.x = d_qbuf[idx + 0]; m |= 1u; }
                if (idx + 1 < n) { q.y = d_qbuf[idx + 1]; m |= 2u; }
                if (idx + 2 < n) { q.z = d_qbuf[idx + 2]; m |= 4u; }
            }
            bool t0 = (m & 1u) && q.x == t;
            bool t1 = (m & 2u) && q.y == t;
            bool t2 = (m & 4u) && q.z == t;
            bool t3 = (m & 8u) && q.w == t;
            unsigned int b0 = __ballot_sync(0xFFFFFFFFu, t0);
            unsigned int b1 = __ballot_sync(0xFFFFFFFFu, t1);
            unsigned int b2 = __ballot_sync(0xFFFFFFFFu, t2);
            unsigned int b3 = __ballot_sync(0xFFFFFFFFu, t3);
            int before = __popc(b0 & ltmask) + __popc(b1 & ltmask) +
                         __popc(b2 & ltmask) + __popc(b3 & ltmask);
            int rank = wbase + run + before;
            run += __popc(b0) + __popc(b1) + __popc(b2) + __popc(b3);

            if (m == 0) continue;

            float o0, o1, o2, o3;
            if (q.x > t) o0 = (float)q.x; else if (t0) { o0 = (rank < r) ? (float)q.x : 0.0f; rank++; } else o0 = 0.0f;
            if (q.y > t) o1 = (float)q.y; else if (t1) { o1 = (rank < r) ? (float)q.y : 0.0f; rank++; } else o1 = 0.0f;
            if (q.z > t) o2 = (float)q.z; else if (t2) { o2 = (rank < r) ? (float)q.z : 0.0f; rank++; } else o2 = 0.0f;
            if (q.w > t) o3 = (float)q.w; else if (t3) { o3 = (rank < r) ? (float)q.w : 0.0f; rank++; } else o3 = 0.0f;

            if (m == 0xFu) {
                float4 ov; ov.x = o0; ov.y = o1; ov.z = o2; ov.w = o3;
                __stcs(reinterpret_cast<float4*>(out + idx), ov);
            } else {
                if (m & 1u) out[idx + 0] = o0;
                if (m & 2u) out[idx + 1] = o1;
                if (m & 4u) out[idx + 2] = o2;
            }
        }
    }

    if (b == 0 && tid == 0 && out_n >= (long long)n + 3) {
        out[n + 0] = d_stats[0];
        out[n + 1] = d_stats[1];
        out[n + 2] = d_stats[2];
    }
}

// ---------------- launch ----------------
static void launch_pdl(void* func, dim3 grid, dim3 block, void** args) {
    cudaLaunchConfig_t cfg = {};
    cfg.gridDim = grid;
    cfg.blockDim = block;
    cudaLaunchAttribute attr[1];
    attr[0].id = cudaLaunchAttributeProgrammaticStreamSerialization;
    attr[0].val.programmaticStreamSerializationAllowed = 1;
    cfg.attrs = attr;
    cfg.numAttrs = 1;
    cudaLaunchKernelExC(&cfg, func, args);
}

extern "C" void kernel_launch(void* const* d_in, const int* in_sizes, int n_in,
                              void* d_out, int out_size) {
    const float* x = (const float*)d_in[0];
    float* out = (float*)d_out;
    int n = in_sizes[0];
    int nb = (n + SEG - 1) / SEG;            // 2048 for 2^24
    int keep = (int)((double)n * 0.5);       // int(total * (1 - SPARSE_RATIO))
    long long out_n = (long long)out_size;

    k_minmax<<<nb, THREADS>>>(x, n);

    {   // PDL: prefetch of x overlaps k_minmax tail
        void* args[] = {(void*)&x, (void*)&n};
        launch_pdl((void*)k_quanthist, dim3(nb), dim3(THREADS), args);
    }
    {   // PDL: selection prologue overlaps k_quanthist tail
        void* args[] = {(void*)&out, (void*)&n, (void*)&keep, (void*)&out_n};
        launch_pdl((void*)k_output, dim3(nb), dim3(THREADS), args);
    }
}

// round 15
// speedup vs baseline: 2.6359x; 2.6359x over previous
#include <cuda_runtime.h>
#include <math_constants.h>

#define THREADS 256
#define SEG 8192              // elements per block in all streaming passes
#define MAXB 4096
#define NELEM_MAX (1 << 24)   // 1*32*4096*128 = 2^24
#define HSTRIDE 257           // hist stride in ints: 257%32==1 -> bank stagger
#define NHIST 16              // two half-warp hists per warp
#define NSLOT 64              // min/max atomic slots

// ---------------- device scratch (no allocations allowed) ----------------
__device__ unsigned int d_umin_arr[NSLOT] = {
    [0 ... NSLOT-1] = 0xFFFFFFFFu };            // re-armed by quanthist last block
__device__ unsigned int d_umax_arr[NSLOT];      // zero-init; re-armed likewise
__device__ int d_hist[256];                     // zeroed by next minmax
__device__ int d_bhT[256][MAXB];                // bin-major per-block histogram
__device__ unsigned char d_qbuf[NELEM_MAX];
__device__ float d_stats[3];                    // min, max, range
__device__ unsigned int d_done = 0;             // quanthist arrival counter

// order-preserving float <-> uint mapping for atomic min/max
__device__ __forceinline__ unsigned int enc_f(float f) {
    unsigned int u = __float_as_uint(f);
    return (u & 0x80000000u) ? ~u : (u | 0x80000000u);
}
__device__ __forceinline__ float dec_f(unsigned int e) {
    unsigned int u = (e & 0x80000000u) ? (e & 0x7FFFFFFFu) : ~e;
    return __uint_as_float(u);
}

// exact quantization matching jnp: ((x-min)/range)*255, round-half-even
__device__ __forceinline__ int quant(float v, float minv, float range) {
    float n = __fdiv_rn(v - minv, range);       // IEEE divide (no fast-math)
    float s = __fmul_rn(n, 255.0f);             // IEEE multiply
    int q = (int)rintf(s);                      // RNE, same as jnp.round
    return min(255, max(0, q));
}

__device__ __forceinline__ void mm4(float4 v, float& mn, float& mx) {
    mn = fminf(mn, fminf(fminf(v.x, v.y), fminf(v.z, v.w)));
    mx = fmaxf(mx, fmaxf(fmaxf(v.x, v.y), fmaxf(v.z, v.w)));
}

// ---------------- pass 1: global min/max (MLP=8) + d_hist re-arm ----------
__global__ void __launch_bounds__(THREADS)
k_minmax(const float* __restrict__ x, int n) {
    int tid = threadIdx.x;
    if (blockIdx.x == 0) d_hist[tid] = 0;   // re-arm for this run's quanthist
    int base = blockIdx.x * SEG;
    float mn = CUDART_INF_F, mx = -CUDART_INF_F;

    if (base + SEG <= n) {
        float4 v[8];
#pragma unroll
        for (int j = 0; j < 8; j++)
            v[j] = *reinterpret_cast<const float4*>(x + base + j * 1024 + tid * 4);
        float mn0 = CUDART_INF_F, mx0 = -CUDART_INF_F;
        float mn1 = CUDART_INF_F, mx1 = -CUDART_INF_F;
#pragma unroll
        for (int j = 0; j < 8; j += 2) {
            mm4(v[j],     mn0, mx0);
            mm4(v[j + 1], mn1, mx1);
        }
        mn = fminf(mn0, mn1);
        mx = fmaxf(mx0, mx1);
    } else {
        for (int i = base + tid; i < n; i += THREADS) {
            float vv = x[i];
            mn = fminf(mn, vv);
            mx = fmaxf(mx, vv);
        }
    }
#pragma unroll
    for (int o = 16; o; o >>= 1) {
        mn = fminf(mn, __shfl_xor_sync(0xFFFFFFFFu, mn, o));
        mx = fmaxf(mx, __shfl_xor_sync(0xFFFFFFFFu, mx, o));
    }
    __shared__ float smin[8], smax[8];
    int lane = tid & 31, wid = tid >> 5;
    if (lane == 0) { smin[wid] = mn; smax[wid] = mx; }
    __syncthreads();
    if (tid == 0) {
#pragma unroll
        for (int w = 1; w < 8; w++) {
            mn = fminf(mn, smin[w]);
            mx = fmaxf(mx, smax[w]);
        }
        int slot = blockIdx.x & (NSLOT - 1);    // 64-way spread: no hot address
        atomicMin(&d_umin_arr[slot], enc_f(mn));
        atomicMax(&d_umax_arr[slot], enc_f(mx));
        __threadfence();
    }
    cudaTriggerProgrammaticLaunchCompletion();
}

// ---------------- pass 2: quantize + histogram (prefetch over PDL sync) ---
__global__ void __launch_bounds__(THREADS)
k_quanthist(const float* __restrict__ x, int n) {
    __shared__ int sh[NHIST * HSTRIDE];   // 16 staggered half-warp hists
    __shared__ unsigned int s_mm[2];
    int tid = threadIdx.x;
    int lane = tid & 31, wid = tid >> 5;
    int* hist = &sh[(wid * 2 + (lane >> 4)) * HSTRIDE];
#pragma unroll
    for (int i = tid; i < NHIST * HSTRIDE; i += THREADS) sh[i] = 0;

    int base = blockIdx.x * SEG;
    bool full = (base + SEG <= n);

    // prefetch iteration 0 (x is input-only: legal before the PDL sync)
    float4 p0, p1, p2, p3;
    if (full) {
        int i0 = base + tid * 4;
        p0 = __ldcs(reinterpret_cast<const float4*>(x + i0));
        p1 = __ldcs(reinterpret_cast<const float4*>(x + i0 + 1024));
        p2 = __ldcs(reinterpret_cast<const float4*>(x + i0 + 2048));
        p3 = __ldcs(reinterpret_cast<const float4*>(x + i0 + 3072));
    }

    // wait for k_minmax grid to complete (PDL)
    cudaGridDependencySynchronize();

    // combine the 64 min/max slots (warp 0), broadcast via smem
    if (wid == 0) {
        unsigned int um = min(d_umin_arr[lane], d_umin_arr[lane + 32]);
        unsigned int ux = max(d_umax_arr[lane], d_umax_arr[lane + 32]);
#pragma unroll
        for (int o = 16; o; o >>= 1) {
            um = min(um, __shfl_xor_sync(0xFFFFFFFFu, um, o));
            ux = max(ux, __shfl_xor_sync(0xFFFFFFFFu, ux, o));
        }
        if (lane == 0) { s_mm[0] = um; s_mm[1] = ux; }
    }
    __syncthreads();
    float minv = dec_f(s_mm[0]), maxv = dec_f(s_mm[1]);
    float range = maxv - minv;
    if (range == 0.0f) range = 1.0f;

    // last-arriving block re-arms slots + snapshots stats (no waiting).
    // Safe: every block increments d_done only after its warp-0 slot reads.
    if (tid == 0) {
        unsigned int prev = atomicAdd(&d_done, 1u);
        if (prev == (unsigned int)(gridDim.x - 1)) {
            d_stats[0] = minv;
            d_stats[1] = maxv;
            d_stats[2] = range;
#pragma unroll
            for (int i = 0; i < NSLOT; i++) {
                d_umin_arr[i] = 0xFFFFFFFFu;
                d_umax_arr[i] = 0u;
            }
            d_done = 0;
        }
    }

    if (full) {
#pragma unroll
        for (int k = 0; k < SEG; k += 4096) {
            int i0 = base + k + tid * 4;
            float4 v0, v1, v2, v3;
            if (k == 0) { v0 = p0; v1 = p1; v2 = p2; v3 = p3; }
            else {
                v0 = __ldcs(reinterpret_cast<const float4*>(x + i0));
                v1 = __ldcs(reinterpret_cast<const float4*>(x + i0 + 1024));
                v2 = __ldcs(reinterpret_cast<const float4*>(x + i0 + 2048));
                v3 = __ldcs(reinterpret_cast<const float4*>(x + i0 + 3072));
            }

            int q00 = quant(v0.x, minv, range), q01 = quant(v0.y, minv, range);
            int q02 = quant(v0.z, minv, range), q03 = quant(v0.w, minv, range);
            int q10 = quant(v1.x, minv, range), q11 = quant(v1.y, minv, range);
            int q12 = quant(v1.z, minv, range), q13 = quant(v1.w, minv, range);
            int q20 = quant(v2.x, minv, range), q21 = quant(v2.y, minv, range);
            int q22 = quant(v2.z, minv, range), q23 = quant(v2.w, minv, range);
            int q30 = quant(v3.x, minv, range), q31 = quant(v3.y, minv, range);
            int q32 = quant(v3.z, minv, range), q33 = quant(v3.w, minv, range);

            atomicAdd(&hist[q00], 1); atomicAdd(&hist[q01], 1);
            atomicAdd(&hist[q02], 1); atomicAdd(&hist[q03], 1);
            atomicAdd(&hist[q10], 1); atomicAdd(&hist[q11], 1);
            atomicAdd(&hist[q12], 1); atomicAdd(&hist[q13], 1);
            atomicAdd(&hist[q20], 1); atomicAdd(&hist[q21], 1);
            atomicAdd(&hist[q22], 1); atomicAdd(&hist[q23], 1);
            atomicAdd(&hist[q30], 1); atomicAdd(&hist[q31], 1);
            atomicAdd(&hist[q32], 1); atomicAdd(&hist[q33], 1);

            *reinterpret_cast<uchar4*>(d_qbuf + i0) =
                make_uchar4((unsigned char)q00, (unsigned char)q01,
                            (unsigned char)q02, (unsigned char)q03);
            *reinterpret_cast<uchar4*>(d_qbuf + i0 + 1024) =
                make_uchar4((unsigned char)q10, (unsigned char)q11,
                            (unsigned char)q12, (unsigned char)q13);
            *reinterpret_cast<uchar4*>(d_qbuf + i0 + 2048) =
                make_uchar4((unsigned char)q20, (unsigned char)q21,
                            (unsigned char)q22, (unsigned char)q23);
            *reinterpret_cast<uchar4*>(d_qbuf + i0 + 3072) =
                make_uchar4((unsigned char)q30, (unsigned char)q31,
                            (unsigned char)q32, (unsigned char)q33);
        }
    } else {
        for (int j = base + tid; j < n; j += THREADS) {
            int q = quant(x[j], minv, range);
            atomicAdd(&hist[q], 1);
            d_qbuf[j] = (unsigned char)q;
        }
    }
    __syncthreads();
    int tot = 0;
#pragma unroll
    for (int h = 0; h < NHIST; h++) tot += sh[h * HSTRIDE + tid];
    atomicAdd(&d_hist[tid], tot);
    d_bhT[tid][blockIdx.x] = tot;     // bin-major: column t is contiguous
    __threadfence();
    cudaTriggerProgrammaticLaunchCompletion();
}

// ---------------- pass 3: per-block selection + sparsified output ---------
__global__ void __launch_bounds__(THREADS)
k_output(float* __restrict__ out, int n, int keep, long long out_n) {
    __shared__ int s_tr[2];
    __shared__ int red[8];
    __shared__ int wsuf[8];
    int tid = threadIdx.x;
    int lane = tid & 31, wid = tid >> 5;
    int b = blockIdx.x;
    int warpbase = b * SEG + wid * 1024;

    // wait for k_quanthist grid — PDL
    cudaGridDependencySynchronize();

    // --- threshold selection: warp suffix scan, ONE barrier ---
    int h = d_hist[tid];
    // inclusive suffix scan within warp (bins tid..warp-end)
    int x = h;
#pragma unroll
    for (int o = 1; o < 32; o <<= 1) {
        int y = __shfl_down_sync(0xFFFFFFFFu, x, o);
        if (lane + o < 32) x += y;
    }
    if (lane == 0) wsuf[wid] = x;    // warp-total (sum of its 32 bins)
    __syncthreads();
    {
        int hi = 0;                   // sum of warp totals for warps > wid
#pragma unroll
        for (int w = 0; w < 8; w++)
            if (w > wid) hi += wsuf[w];
        int ge = x + hi;              // count(q >= tid)
        int gt = ge - h;
        if (gt < keep && ge >= keep) { s_tr[0] = tid; s_tr[1] = keep - gt; }
    }
    __syncthreads();
    int t = s_tr[0], r = s_tr[1];

    // --- own tie prefix: s = sum d_bhT[t][0..b), contiguous L2-hot ---
    const int* col = d_bhT[t];
    int part = 0;
    for (int j = tid; j < b; j += THREADS) part += col[j];
#pragma unroll
    for (int o = 16; o; o >>= 1) part += __shfl_xor_sync(0xFFFFFFFFu, part, o);
    if (lane == 0) red[wid] = part;
    __syncthreads();
    int s = red[0];
#pragma unroll
    for (int w = 1; w < 8; w++) s += red[w];
    int e = s + col[b];

    if (e <= r || s >= r) {
        // ---- fast path: keep q >= keepv, front-batched loads (MLP=8) ----
        int keepv = (e <= r) ? t : (t + 1);
        if (b * SEG + SEG <= n) {
            uchar4 qv[8];
#pragma unroll
            for (int rr = 0; rr < 8; rr++)
                qv[rr] = *reinterpret_cast<const uchar4*>(
                    d_qbuf + warpbase + rr * 128 + lane * 4);
#pragma unroll
            for (int rr = 0; rr < 8; rr++) {
                uchar4 q = qv[rr];
                float4 ov;
                ov.x = (q.x >= keepv) ? (float)q.x : 0.0f;
                ov.y = (q.y >= keepv) ? (float)q.y : 0.0f;
                ov.z = (q.z >= keepv) ? (float)q.z : 0.0f;
                ov.w = (q.w >= keepv) ? (float)q.w : 0.0f;
                __stcs(reinterpret_cast<float4*>(out + warpbase + rr * 128 + lane * 4), ov);
            }
        } else {
            for (int rr = 0; rr < 8; rr++) {
                int idx = warpbase + rr * 128 + lane * 4;
                for (int m = 0; m < 4; m++) {
                    int j = idx + m;
                    if (j < n) {
                        int q = d_qbuf[j];
                        out[j] = (q >= keepv) ? (float)q : 0.0f;
                    }
                }
            }
        }
    } else {
        // ---- partial path: exactly one block — two-phase ballot ranking ----
        __shared__ int s_wtot[8];
        unsigned int ltmask = (1u << lane) - 1u;

        int wcnt = 0;
#pragma unroll
        for (int rr = 0; rr < 8; rr++) {
            int idx = warpbase + rr * 128 + lane * 4;
            uchar4 q = make_uchar4(255, 255, 255, 255);
            unsigned int m = 0;
            if (idx + 3 < n) {
                q = *reinterpret_cast<const uchar4*>(d_qbuf + idx);
                m = 0xFu;
            } else {
                if (idx + 0 < n) { q.x = d_qbuf[idx + 0]; m |= 1u; }
                if (idx + 1 < n) { q.y = d_qbuf[idx + 1]; m |= 2u; }
                if (idx + 2 < n) { q.z = d_qbuf[idx + 2]; m |= 4u; }
            }
            unsigned int b0 = __ballot_sync(0xFFFFFFFFu, (m & 1u) && q.x == t);
            unsigned int b1 = __ballot_sync(0xFFFFFFFFu, (m & 2u) && q.y == t);
            unsigned int b2 = __ballot_sync(0xFFFFFFFFu, (m & 4u) && q.z == t);
            unsigned int b3 = __ballot_sync(0xFFFFFFFFu, (m & 8u) && q.w == t);
            wcnt += __popc(b0) + __popc(b1) + __popc(b2) + __popc(b3);
        }
        if (lane == 0) s_wtot[wid] = wcnt;
        __syncthreads();

        int wbase = s;
#pragma unroll
        for (int w = 0; w < 8; w++)
            if (w < wid) wbase += s_wtot[w];

        int run = 0;
#pragma unroll
        for (int rr = 0; rr < 8; rr++) {
            int idx = warpbase + rr * 128 + lane * 4;
            uchar4 q = make_uchar4(255, 255, 255, 255);
            unsigned int m = 0;
            if (idx + 3 < n) {
                q = *reinterpret_cast<const uchar4*>(d_qbuf + idx);
                m = 0xFu;
            } else {
                if (idx + 0 < n) { q.x = d_qbuf[idx + 0]; m |= 1u; }
                if (idx + 1 < n) { q.y = d_qbuf[idx + 1]; m |= 2u; }
                if (idx + 2 < n) { q.z = d_qbuf[idx + 2]; m |= 4u; }
            }
            bool t0 = (m & 1u) && q.x == t;
            bool t1 = (m & 2u) && q.y == t;
            bool t2 = (m & 4u) && q.z == t;
            bool t3 = (m & 8u) && q.w == t;
            unsigned int b0 = __ballot_sync(0xFFFFFFFFu, t0);
            unsigned int b1 = __ballot_sync(0xFFFFFFFFu, t1);
            unsigned int b2 = __ballot_sync(0xFFFFFFFFu, t2);
            unsigned int b3 = __ballot_sync(0xFFFFFFFFu, t3);
            int before = __popc(b0 & ltmask) + __popc(b1 & ltmask) +
                         __popc(b2 & ltmask) + __popc(b3 & ltmask);
            int rank = wbase + run + before;
            run += __popc(b0) + __popc(b1) + __popc(b2) + __popc(b3);

            if (m == 0) continue;

            float o0, o1, o2, o3;
            if (q.x > t) o0 = (float)q.x; else if (t0) { o0 = (rank < r) ? (float)q.x : 0.0f; rank++; } else o0 = 0.0f;
            if (q.y > t) o1 = (float)q.y; else if (t1) { o1 = (rank < r) ? (float)q.y : 0.0f; rank++; } else o1 = 0.0f;
            if (q.z > t) o2 = (float)q.z; else if (t2) { o2 = (rank < r) ? (float)q.z : 0.0f; rank++; } else o2 = 0.0f;
            if (q.w > t) o3 = (float)q.w; else if (t3) { o3 = (rank < r) ? (float)q.w : 0.0f; rank++; } else o3 = 0.0f;

            if (m == 0xFu) {
                float4 ov; ov.x = o0; ov.y = o1; ov.z = o2; ov.w = o3;
                __stcs(reinterpret_cast<float4*>(out + idx), ov);
            } else {
                if (m & 1u) out[idx + 0] = o0;
                if (m & 2u) out[idx + 1] = o1;
                if (m & 4u) out[idx + 2] = o2;
            }
        }
    }

    if (b == 0 && tid == 0 && out_n >= (long long)n + 3) {
        out[n + 0] = d_stats[0];
        out[n + 1] = d_stats[1];
        out[n + 2] = d_stats[2];
    }
}

// ---------------- launch ----------------
static void launch_pdl(void* func, dim3 grid, dim3 block, void** args) {
    cudaLaunchConfig_t cfg = {};
    cfg.gridDim = grid;
    cfg.blockDim = block;
    cudaLaunchAttribute attr[1];
    attr[0].id = cudaLaunchAttributeProgrammaticStreamSerialization;
    attr[0].val.programmaticStreamSerializationAllowed = 1;
    cfg.attrs = attr;
    cfg.numAttrs = 1;
    cudaLaunchKernelExC(&cfg, func, args);
}

extern "C" void kernel_launch(void* const* d_in, const int* in_sizes, int n_in,
                              void* d_out, int out_size) {
    const float* x = (const float*)d_in[0];
    float* out = (float*)d_out;
    int n = in_sizes[0];
    int nb = (n + SEG - 1) / SEG;            // 2048 for 2^24
    int keep = (int)((double)n * 0.5);       // int(total * (1 - SPARSE_RATIO))
    long long out_n = (long long)out_size;

    k_minmax<<<nb, THREADS>>>(x, n);

    {   // PDL: prefetch of x overlaps k_minmax tail
        void* args[] = {(void*)&x, (void*)&n};
        launch_pdl((void*)k_quanthist, dim3(nb), dim3(THREADS), args);
    }
    {   // PDL: selection prologue overlaps k_quanthist tail
        void* args[] = {(void*)&out, (void*)&n, (void*)&keep, (void*)&out_n};
        launch_pdl((void*)k_output, dim3(nb), dim3(THREADS), args);
    }
}

// round 16
// speedup vs baseline: 2.7653x; 1.0491x over previous
#include <cuda_runtime.h>
#include <math_constants.h>

#define THREADS 256
#define SEG 8192              // elements per block in all streaming passes
#define MAXB 4096
#define NELEM_MAX (1 << 24)   // 1*32*4096*128 = 2^24
#define HSTRIDE 257           // hist stride in ints: 257%32==1 -> bank stagger
#define NHIST 16              // two half-warp hists per warp
#define NSLOT 64              // min/max atomic slots

// ---------------- device scratch (no allocations allowed) ----------------
__device__ unsigned int d_umin_arr[NSLOT] = {
    [0 ... NSLOT-1] = 0xFFFFFFFFu };            // re-armed by quanthist last block
__device__ unsigned int d_umax_arr[NSLOT];      // zero-init; re-armed likewise
__device__ int d_hist[256];                     // zeroed by next minmax
__device__ int d_bhT[256][MAXB];                // bin-major per-block histogram
__device__ unsigned char d_qbuf[NELEM_MAX];
__device__ float d_stats[3];                    // min, max, range
__device__ unsigned int d_done = 0;             // quanthist arrival counter

// order-preserving float <-> uint mapping for atomic min/max
__device__ __forceinline__ unsigned int enc_f(float f) {
    unsigned int u = __float_as_uint(f);
    return (u & 0x80000000u) ? ~u : (u | 0x80000000u);
}
__device__ __forceinline__ float dec_f(unsigned int e) {
    unsigned int u = (e & 0x80000000u) ? (e & 0x7FFFFFFFu) : ~e;
    return __uint_as_float(u);
}

// quantization via precomputed reciprocal: (v-min)*rcp*255, round-half-even.
// Differs from __fdiv_rn by <=~1 ulp -> rint flips are ~2^-23/element rare.
__device__ __forceinline__ int quant(float v, float minv, float rcp) {
    float n = __fmul_rn(v - minv, rcp);         // IEEE multiply
    float s = __fmul_rn(n, 255.0f);             // IEEE multiply
    int q = (int)rintf(s);                      // RNE, same as jnp.round
    return min(255, max(0, q));
}

__device__ __forceinline__ void mm4(float4 v, float& mn, float& mx) {
    mn = fminf(mn, fminf(fminf(v.x, v.y), fminf(v.z, v.w)));
    mx = fmaxf(mx, fmaxf(fmaxf(v.x, v.y), fmaxf(v.z, v.w)));
}

// ---------------- pass 1: global min/max (MLP=8) + d_hist re-arm ----------
__global__ void __launch_bounds__(THREADS)
k_minmax(const float* __restrict__ x, int n) {
    int tid = threadIdx.x;
    if (blockIdx.x == 0) d_hist[tid] = 0;   // re-arm for this run's quanthist
    int base = blockIdx.x * SEG;
    float mn = CUDART_INF_F, mx = -CUDART_INF_F;

    if (base + SEG <= n) {
        float4 v[8];
#pragma unroll
        for (int j = 0; j < 8; j++)
            v[j] = *reinterpret_cast<const float4*>(x + base + j * 1024 + tid * 4);
        float mn0 = CUDART_INF_F, mx0 = -CUDART_INF_F;
        float mn1 = CUDART_INF_F, mx1 = -CUDART_INF_F;
#pragma unroll
        for (int j = 0; j < 8; j += 2) {
            mm4(v[j],     mn0, mx0);
            mm4(v[j + 1], mn1, mx1);
        }
        mn = fminf(mn0, mn1);
        mx = fmaxf(mx0, mx1);
    } else {
        for (int i = base + tid; i < n; i += THREADS) {
            float vv = x[i];
            mn = fminf(mn, vv);
            mx = fmaxf(mx, vv);
        }
    }
#pragma unroll
    for (int o = 16; o; o >>= 1) {
        mn = fminf(mn, __shfl_xor_sync(0xFFFFFFFFu, mn, o));
        mx = fmaxf(mx, __shfl_xor_sync(0xFFFFFFFFu, mx, o));
    }
    __shared__ float smin[8], smax[8];
    int lane = tid & 31, wid = tid >> 5;
    if (lane == 0) { smin[wid] = mn; smax[wid] = mx; }
    __syncthreads();
    if (tid == 0) {
#pragma unroll
        for (int w = 1; w < 8; w++) {
            mn = fminf(mn, smin[w]);
            mx = fmaxf(mx, smax[w]);
        }
        int slot = blockIdx.x & (NSLOT - 1);    // 64-way spread: no hot address
        atomicMin(&d_umin_arr[slot], enc_f(mn));
        atomicMax(&d_umax_arr[slot], enc_f(mx));
        __threadfence();
    }
    cudaTriggerProgrammaticLaunchCompletion();
}

// ---------------- pass 2: quantize + histogram (prefetch over PDL sync) ---
__global__ void __launch_bounds__(THREADS)
k_quanthist(const float* __restrict__ x, int n) {
    __shared__ int sh[NHIST * HSTRIDE];   // 16 staggered half-warp hists
    __shared__ unsigned int s_mm[2];
    int tid = threadIdx.x;
    int lane = tid & 31, wid = tid >> 5;
    int* hist = &sh[(wid * 2 + (lane >> 4)) * HSTRIDE];
#pragma unroll
    for (int i = tid; i < NHIST * HSTRIDE; i += THREADS) sh[i] = 0;

    int base = blockIdx.x * SEG;
    bool full = (base + SEG <= n);

    // prefetch iteration 0 (x is input-only: legal before the PDL sync)
    float4 p0, p1, p2, p3;
    if (full) {
        int i0 = base + tid * 4;
        p0 = __ldcs(reinterpret_cast<const float4*>(x + i0));
        p1 = __ldcs(reinterpret_cast<const float4*>(x + i0 + 1024));
        p2 = __ldcs(reinterpret_cast<const float4*>(x + i0 + 2048));
        p3 = __ldcs(reinterpret_cast<const float4*>(x + i0 + 3072));
    }

    // wait for k_minmax grid to complete (PDL)
    cudaGridDependencySynchronize();

    // combine the 64 min/max slots (warp 0), broadcast via smem
    if (wid == 0) {
        unsigned int um = min(d_umin_arr[lane], d_umin_arr[lane + 32]);
        unsigned int ux = max(d_umax_arr[lane], d_umax_arr[lane + 32]);
#pragma unroll
        for (int o = 16; o; o >>= 1) {
            um = min(um, __shfl_xor_sync(0xFFFFFFFFu, um, o));
            ux = max(ux, __shfl_xor_sync(0xFFFFFFFFu, ux, o));
        }
        if (lane == 0) { s_mm[0] = um; s_mm[1] = ux; }
    }
    __syncthreads();
    float minv = dec_f(s_mm[0]), maxv = dec_f(s_mm[1]);
    float range = maxv - minv;
    if (range == 0.0f) range = 1.0f;
    float rcp = __fdiv_rn(1.0f, range);   // one correctly-rounded div per block

    // last-arriving block re-arms slots + snapshots stats (no waiting).
    // Safe: every block increments d_done only after its warp-0 slot reads.
    if (tid == 0) {
        unsigned int prev = atomicAdd(&d_done, 1u);
        if (prev == (unsigned int)(gridDim.x - 1)) {
            d_stats[0] = minv;
            d_stats[1] = maxv;
            d_stats[2] = range;
#pragma unroll
            for (int i = 0; i < NSLOT; i++) {
                d_umin_arr[i] = 0xFFFFFFFFu;
                d_umax_arr[i] = 0u;
            }
            d_done = 0;
        }
    }

    if (full) {
#pragma unroll
        for (int k = 0; k < SEG; k += 4096) {
            int i0 = base + k + tid * 4;
            float4 v0, v1, v2, v3;
            if (k == 0) { v0 = p0; v1 = p1; v2 = p2; v3 = p3; }
            else {
                v0 = __ldcs(reinterpret_cast<const float4*>(x + i0));
                v1 = __ldcs(reinterpret_cast<const float4*>(x + i0 + 1024));
                v2 = __ldcs(reinterpret_cast<const float4*>(x + i0 + 2048));
                v3 = __ldcs(reinterpret_cast<const float4*>(x + i0 + 3072));
            }

            int q00 = quant(v0.x, minv, rcp), q01 = quant(v0.y, minv, rcp);
            int q02 = quant(v0.z, minv, rcp), q03 = quant(v0.w, minv, rcp);
            int q10 = quant(v1.x, minv, rcp), q11 = quant(v1.y, minv, rcp);
            int q12 = quant(v1.z, minv, rcp), q13 = quant(v1.w, minv, rcp);
            int q20 = quant(v2.x, minv, rcp), q21 = quant(v2.y, minv, rcp);
            int q22 = quant(v2.z, minv, rcp), q23 = quant(v2.w, minv, rcp);
            int q30 = quant(v3.x, minv, rcp), q31 = quant(v3.y, minv, rcp);
            int q32 = quant(v3.z, minv, rcp), q33 = quant(v3.w, minv, rcp);

            atomicAdd(&hist[q00], 1); atomicAdd(&hist[q01], 1);
            atomicAdd(&hist[q02], 1); atomicAdd(&hist[q03], 1);
            atomicAdd(&hist[q10], 1); atomicAdd(&hist[q11], 1);
            atomicAdd(&hist[q12], 1); atomicAdd(&hist[q13], 1);
            atomicAdd(&hist[q20], 1); atomicAdd(&hist[q21], 1);
            atomicAdd(&hist[q22], 1); atomicAdd(&hist[q23], 1);
            atomicAdd(&hist[q30], 1); atomicAdd(&hist[q31], 1);
            atomicAdd(&hist[q32], 1); atomicAdd(&hist[q33], 1);

            *reinterpret_cast<uchar4*>(d_qbuf + i0) =
                make_uchar4((unsigned char)q00, (unsigned char)q01,
                            (unsigned char)q02, (unsigned char)q03);
            *reinterpret_cast<uchar4*>(d_qbuf + i0 + 1024) =
                make_uchar4((unsigned char)q10, (unsigned char)q11,
                            (unsigned char)q12, (unsigned char)q13);
            *reinterpret_cast<uchar4*>(d_qbuf + i0 + 2048) =
                make_uchar4((unsigned char)q20, (unsigned char)q21,
                            (unsigned char)q22, (unsigned char)q23);
            *reinterpret_cast<uchar4*>(d_qbuf + i0 + 3072) =
                make_uchar4((unsigned char)q30, (unsigned char)q31,
                            (unsigned char)q32, (unsigned char)q33);
        }
    } else {
        for (int j = base + tid; j < n; j += THREADS) {
            int q = quant(x[j], minv, rcp);
            atomicAdd(&hist[q], 1);
            d_qbuf[j] = (unsigned char)q;
        }
    }
    __syncthreads();
    int tot = 0;
#pragma unroll
    for (int h = 0; h < NHIST; h++) tot += sh[h * HSTRIDE + tid];
    atomicAdd(&d_hist[tid], tot);
    d_bhT[tid][blockIdx.x] = tot;     // bin-major: column t is contiguous
    __threadfence();
    cudaTriggerProgrammaticLaunchCompletion();
}

// ---------------- pass 3: per-block selection + sparsified output ---------
__global__ void __launch_bounds__(THREADS)
k_output(float* __restrict__ out, int n, int keep, long long out_n) {
    __shared__ int s_tr[2];
    __shared__ int red[8];
    __shared__ int wsuf[8];
    int tid = threadIdx.x;
    int lane = tid & 31, wid = tid >> 5;
    int b = blockIdx.x;
    int warpbase = b * SEG + wid * 1024;

    // wait for k_quanthist grid — PDL
    cudaGridDependencySynchronize();

    // --- threshold selection: warp suffix scan, ONE barrier ---
    int h = d_hist[tid];
    int x = h;
#pragma unroll
    for (int o = 1; o < 32; o <<= 1) {
        int y = __shfl_down_sync(0xFFFFFFFFu, x, o);
        if (lane + o < 32) x += y;
    }
    if (lane == 0) wsuf[wid] = x;    // warp-total (sum of its 32 bins)
    __syncthreads();
    {
        int hi = 0;                   // sum of warp totals for warps > wid
#pragma unroll
        for (int w = 0; w < 8; w++)
            if (w > wid) hi += wsuf[w];
        int ge = x + hi;              // count(q >= tid)
        int gt = ge - h;
        if (gt < keep && ge >= keep) { s_tr[0] = tid; s_tr[1] = keep - gt; }
    }
    __syncthreads();
    int t = s_tr[0], r = s_tr[1];

    // --- own tie prefix: s = sum d_bhT[t][0..b), contiguous L2-hot ---
    const int* col = d_bhT[t];
    int part = 0;
    for (int j = tid; j < b; j += THREADS) part += col[j];
#pragma unroll
    for (int o = 16; o; o >>= 1) part += __shfl_xor_sync(0xFFFFFFFFu, part, o);
    if (lane == 0) red[wid] = part;
    __syncthreads();
    int s = red[0];
#pragma unroll
    for (int w = 1; w < 8; w++) s += red[w];
    int e = s + col[b];

    if (e <= r || s >= r) {
        // ---- fast path: keep q >= keepv, front-batched loads (MLP=8) ----
        int keepv = (e <= r) ? t : (t + 1);
        if (b * SEG + SEG <= n) {
            uchar4 qv[8];
#pragma unroll
            for (int rr = 0; rr < 8; rr++)
                qv[rr] = *reinterpret_cast<const uchar4*>(
                    d_qbuf + warpbase + rr * 128 + lane * 4);
#pragma unroll
            for (int rr = 0; rr < 8; rr++) {
                uchar4 q = qv[rr];
                float4 ov;
                ov.x = (q.x >= keepv) ? (float)q.x : 0.0f;
                ov.y = (q.y >= keepv) ? (float)q.y : 0.0f;
                ov.z = (q.z >= keepv) ? (float)q.z : 0.0f;
                ov.w = (q.w >= keepv) ? (float)q.w : 0.0f;
                __stcs(reinterpret_cast<float4*>(out + warpbase + rr * 128 + lane * 4), ov);
            }
        } else {
            for (int rr = 0; rr < 8; rr++) {
                int idx = warpbase + rr * 128 + lane * 4;
                for (int m = 0; m < 4; m++) {
                    int j = idx + m;
                    if (j < n) {
                        int q = d_qbuf[j];
                        out[j] = (q >= keepv) ? (float)q : 0.0f;
                    }
                }
            }
        }
    } else {
        // ---- partial path: exactly one block — two-phase ballot ranking ----
        __shared__ int s_wtot[8];
        unsigned int ltmask = (1u << lane) - 1u;

        int wcnt = 0;
#pragma unroll
        for (int rr = 0; rr < 8; rr++) {
            int idx = warpbase + rr * 128 + lane * 4;
            uchar4 q = make_uchar4(255, 255, 255, 255);
            unsigned int m = 0;
            if (idx + 3 < n) {
                q = *reinterpret_cast<const uchar4*>(d_qbuf + idx);
                m = 0xFu;
            } else {
                if (idx + 0 < n) { q.x = d_qbuf[idx + 0]; m |= 1u; }
                if (idx + 1 < n) { q.y = d_qbuf[idx + 1]; m |= 2u; }
                if (idx + 2 < n) { q.z = d_qbuf[idx + 2]; m |= 4u; }
            }
            unsigned int b0 = __ballot_sync(0xFFFFFFFFu, (m & 1u) && q.x == t);
            unsigned int b1 = __ballot_sync(0xFFFFFFFFu, (m & 2u) && q.y == t);
            unsigned int b2 = __ballot_sync(0xFFFFFFFFu, (m & 4u) && q.z == t);
            unsigned int b3 = __ballot_sync(0xFFFFFFFFu, (m & 8u) && q.w == t);
            wcnt += __popc(b0) + __popc(b1) + __popc(b2) + __popc(b3);
        }
        if (lane == 0) s_wtot[wid] = wcnt;
        __syncthreads();

        int wbase = s;
#pragma unroll
        for (int w = 0; w < 8; w++)
            if (w < wid) wbase += s_wtot[w];

        int run = 0;
#pragma unroll
        for (int rr = 0; rr < 8; rr++) {
            int idx = warpbase + rr * 128 + lane * 4;
            uchar4 q = make_uchar4(255, 255, 255, 255);
            unsigned int m = 0;
            if (idx + 3 < n) {
                q = *reinterpret_cast<const uchar4*>(d_qbuf + idx);
                m = 0xFu;
            } else {
                if (idx + 0 < n) { q.x = d_qbuf[idx + 0]; m |= 1u; }
                if (idx + 1 < n) { q.y = d_qbuf[idx + 1]; m |= 2u; }
                if (idx + 2 < n) { q.z = d_qbuf[idx + 2]; m |= 4u; }
            }
            bool t0 = (m & 1u) && q.x == t;
            bool t1 = (m & 2u) && q.y == t;
            bool t2 = (m & 4u) && q.z == t;
            bool t3 = (m & 8u) && q.w == t;
            unsigned int b0 = __ballot_sync(0xFFFFFFFFu, t0);
            unsigned int b1 = __ballot_sync(0xFFFFFFFFu, t1);
            unsigned int b2 = __ballot_sync(0xFFFFFFFFu, t2);
            unsigned int b3 = __ballot_sync(0xFFFFFFFFu, t3);
            int before = __popc(b0 & ltmask) + __popc(b1 & ltmask) +
                         __popc(b2 & ltmask) + __popc(b3 & ltmask);
            int rank = wbase + run + before;
            run += __popc(b0) + __popc(b1) + __popc(b2) + __popc(b3);

            if (m == 0) continue;

            float o0, o1, o2, o3;
            if (q.x > t) o0 = (float)q.x; else if (t0) { o0 = (rank < r) ? (float)q.x : 0.0f; rank++; } else o0 = 0.0f;
            if (q.y > t) o1 = (float)q.y; else if (t1) { o1 = (rank < r) ? (float)q.y : 0.0f; rank++; } else o1 = 0.0f;
            if (q.z > t) o2 = (float)q.z; else if (t2) { o2 = (rank < r) ? (float)q.z : 0.0f; rank++; } else o2 = 0.0f;
            if (q.w > t) o3 = (float)q.w; else if (t3) { o3 = (rank < r) ? (float)q.w : 0.0f; rank++; } else o3 = 0.0f;

            if (m == 0xFu) {
                float4 ov; ov.x = o0; ov.y = o1; ov.z = o2; ov.w = o3;
                __stcs(reinterpret_cast<float4*>(out + idx), ov);
            } else {
                if (m & 1u) out[idx + 0] = o0;
                if (m & 2u) out[idx + 1] = o1;
                if (m & 4u) out[idx + 2] = o2;
            }
        }
    }

    if (b == 0 && tid == 0 && out_n >= (long long)n + 3) {
        out[n + 0] = d_stats[0];
        out[n + 1] = d_stats[1];
        out[n + 2] = d_stats[2];
    }
}

// ---------------- launch ----------------
static void launch_pdl(void* func, dim3 grid, dim3 block, void** args) {
    cudaLaunchConfig_t cfg = {};
    cfg.gridDim = grid;
    cfg.blockDim = block;
    cudaLaunchAttribute attr[1];
    attr[0].id = cudaLaunchAttributeProgrammaticStreamSerialization;
    attr[0].val.programmaticStreamSerializationAllowed = 1;
    cfg.attrs = attr;
    cfg.numAttrs = 1;
    cudaLaunchKernelExC(&cfg, func, args);
}

extern "C" void kernel_launch(void* const* d_in, const int* in_sizes, int n_in,
                              void* d_out, int out_size) {
    const float* x = (const float*)d_in[0];
    float* out = (float*)d_out;
    int n = in_sizes[0];
    int nb = (n + SEG - 1) / SEG;            // 2048 for 2^24
    int keep = (int)((double)n * 0.5);       // int(total * (1 - SPARSE_RATIO))
    long long out_n = (long long)out_size;

    k_minmax<<<nb, THREADS>>>(x, n);

    {   // PDL: prefetch of x overlaps k_minmax tail
        void* args[] = {(void*)&x, (void*)&n};
        launch_pdl((void*)k_quanthist, dim3(nb), dim3(THREADS), args);
    }
    {   // PDL: selection prologue overlaps k_quanthist tail
        void* args[] = {(void*)&out, (void*)&n, (void*)&keep, (void*)&out_n};
        launch_pdl((void*)k_output, dim3(nb), dim3(THREADS), args);
    }
}